// round 8
// baseline (speedup 1.0000x reference)
#include <cuda_runtime.h>
#include <cstdint>

#define Bt    1024
#define Tt    1000
#define HH    256
#define NBLK  128
#define NTHR  512
#define ICC   48              // W2/W3 rows resident in SMEM (6 iterations of 8)
#define CHROWS 16             // rows per streamed chunk (2 iterations of 8)
#define NCH   13              // chunks per layer: (256-48)/16
#define NKTOT (2*NCH)         // 26
#define NSTG  4               // pipeline stages (issue 3 ahead, wait_group 2)
#define HSTR  20              // dup-activation row stride (conflict-free)

using u64 = unsigned long long;

__device__ __forceinline__ u64 ffma2(u64 a, u64 b, u64 c) {
    u64 d; asm("fma.rn.f32x2 %0,%1,%2,%3;" : "=l"(d) : "l"(a), "l"(b), "l"(c)); return d;
}
__device__ __forceinline__ u64 addf2(u64 a, u64 b) {
    u64 d; asm("add.rn.f32x2 %0,%1,%2;" : "=l"(d) : "l"(a), "l"(b)); return d;
}
__device__ __forceinline__ u64 pack2(float x, float y) {
    u64 d; asm("mov.b64 %0,{%1,%2};" : "=l"(d) : "f"(x), "f"(y)); return d;
}
__device__ __forceinline__ float2 unpack2(u64 a) {
    float2 f; asm("mov.b64 {%0,%1},%2;" : "=f"(f.x), "=f"(f.y) : "l"(a)); return f;
}
__device__ __forceinline__ float elu1(float v) { return v > 0.f ? v : (__expf(v) - 1.f); }

// ---------------- SMEM layout (float offsets) ----------------
#define OFF_W2   0                      // 48*256 = 12288
#define OFF_W3   12288                  // 12288
#define OFF_STR  24576                  // 4*16*256 = 16384
#define OFF_HA   40960                  // 256*20 = 5120 (dup, padded)
#define OFF_HB   46080                  // 5120
#define OFF_H3   51200                  // 8*260 = 2080
#define OFF_W4   53280                  // 8*260 = 2080
#define OFF_INP  55360                  // 16*16 = 256 (dup, stride 16)
#define OFF_SCR  55616                  // 2176: union{red[512], reduce-scratch 64x17 u64, araw}
#define OFF_ZJ   57792                  // 64
#define OFF_EVT  57856                  // 8
#define OFF_B4   57864                  // 8
#define OFF_TSH  57872                  // 2
#define SM_FLOATS 57874
#define SM_BYTES  (SM_FLOATS * 4)       // 231496 B (< 232448 cap)

#define STG_FLOATS (CHROWS * HH)        // 4096

// one weight-row accumulation: acc{0,1}[g] += h[g] * (w pair); h rows stride HSTR
__device__ __forceinline__ void accum_iter(const float* __restrict__ wrow_j0,
                                           const float* __restrict__ hrow,
                                           u64* __restrict__ acc0, u64* __restrict__ acc1) {
    ulonglong2 w = *(const ulonglong2*)wrow_j0;   // (w_j0,w_j1),(w_j2,w_j3)
    u64 hv[8];
    *(ulonglong2*)&hv[0] = *(const ulonglong2*)(hrow);
    *(ulonglong2*)&hv[2] = *(const ulonglong2*)(hrow + 4);
    *(ulonglong2*)&hv[4] = *(const ulonglong2*)(hrow + 8);
    *(ulonglong2*)&hv[6] = *(const ulonglong2*)(hrow + 12);
#pragma unroll
    for (int g = 0; g < 8; g++) {
        acc0[g] = ffma2(hv[g], w.x, acc0[g]);
        acc1[g] = ffma2(hv[g], w.y, acc1[g]);
    }
}

__device__ __forceinline__ void issue_chunk(int k, unsigned str_u32,
                                            const float* __restrict__ W2,
                                            const float* __restrict__ W3, int tid) {
    if (k >= NKTOT) return;
    const int kl = (k < NCH) ? k : (k - NCH);
    const char* src = (const char*)((k < NCH ? W2 : W3) + (ICC + kl * CHROWS) * HH);
    unsigned dst = str_u32 + (unsigned)(k % NSTG) * (STG_FLOATS * 4);
#pragma unroll
    for (int r = 0; r < 2; r++) {
        unsigned off = (unsigned)(tid + r * NTHR) * 16;
        asm volatile("cp.async.cg.shared.global [%0], [%1], 16;" :: "r"(dst + off), "l"(src + off));
    }
    asm volatile("cp.async.commit_group;");
}

// full 256->256 layer, 512 threads: j-quad x 8 batches x K-eighth,
// butterfly ^8,^16 + cross-warp-pair SMEM reduce, bias+ELU+writeback by even warps
template <bool TO_H3P>
__device__ __forceinline__ void biglayerB(
    const float* __restrict__ wc, const float* __restrict__ strb,
    const float* __restrict__ W2, const float* __restrict__ W3,
    const float* __restrict__ hsrc, float* __restrict__ hdst,
    u64* __restrict__ scr64,
    int j0, int kq8, int quad, int layer, ulonglong2 bq,
    unsigned str_u32, int tid, int warp, int lane)
{
    u64 acc0[8], acc1[8];
#pragma unroll
    for (int g = 0; g < 8; g++) { acc0[g] = 0ull; acc1[g] = 0ull; }

    // cached rows: n = 0..5, this lane handles row 8n+kq8
#pragma unroll 2
    for (int n = 0; n < ICC / 8; n++) {
        int i = n * 8 + kq8;
        accum_iter(wc + i * HH + j0, hsrc + i * HSTR, acc0, acc1);
    }
    // streamed chunks (16 rows = 2 iterations each)
#pragma unroll 1
    for (int c = 0; c < NCH; c++) {
        const int k = layer * NCH + c;
        if (k < NKTOT - 2)       asm volatile("cp.async.wait_group 2;" ::: "memory");
        else if (k == NKTOT - 2) asm volatile("cp.async.wait_group 1;" ::: "memory");
        else                     asm volatile("cp.async.wait_group 0;" ::: "memory");
        __syncthreads();
        issue_chunk(k + 3, str_u32, W2, W3, tid);
        const float* sb = strb + (k % NSTG) * STG_FLOATS;
        const int base = ICC + c * CHROWS;
#pragma unroll
        for (int m = 0; m < 2; m++) {
            int io = m * 8 + kq8;
            accum_iter(sb + io * HH + j0, hsrc + (base + io) * HSTR, acc0, acc1);
        }
    }

    // intra-warp K-reduction over lane>>3 (4 of the 8 kq8 values)
#pragma unroll
    for (int g = 0; g < 8; g++) {
        acc0[g] = addf2(acc0[g], __shfl_xor_sync(0xffffffffu, acc0[g], 8));
        acc0[g] = addf2(acc0[g], __shfl_xor_sync(0xffffffffu, acc0[g], 16));
        acc1[g] = addf2(acc1[g], __shfl_xor_sync(0xffffffffu, acc1[g], 8));
        acc1[g] = addf2(acc1[g], __shfl_xor_sync(0xffffffffu, acc1[g], 16));
    }

    const int g2 = (lane >> 3) * 2;
    if (warp & 1) {
        // odd warp holds sum over kq8 4..7: publish its quarter to scratch
        u64* p = scr64 + quad * 17;
        p[g2]     = acc0[g2];
        p[g2 + 1] = acc0[g2 + 1];
        p[8 + g2] = acc1[g2];
        p[9 + g2] = acc1[g2 + 1];
    }
    __syncthreads();
    if (!(warp & 1)) {
        const u64* p = scr64 + quad * 17;
        u64 s00 = addf2(acc0[g2],     p[g2]);
        u64 s01 = addf2(acc0[g2 + 1], p[g2 + 1]);
        u64 s10 = addf2(acc1[g2],     p[8 + g2]);
        u64 s11 = addf2(acc1[g2 + 1], p[9 + g2]);

        float2 bp  = unpack2(bq.x);   // bias (j0, j0+1)
        float2 bp2 = unpack2(bq.y);   // bias (j0+2, j0+3)
        float2 va = unpack2(s00), vb = unpack2(s01);
        float a0 = elu1(va.x + bp.x),  a1 = elu1(vb.x + bp.x);    // j0   : g=g2, g2+1
        float c0 = elu1(va.y + bp.y),  c1 = elu1(vb.y + bp.y);    // j0+1
        float2 vc = unpack2(s10), vd = unpack2(s11);
        float d0 = elu1(vc.x + bp2.x), d1 = elu1(vd.x + bp2.x);   // j0+2
        float e0 = elu1(vc.y + bp2.y), e1 = elu1(vd.y + bp2.y);   // j0+3

        if (TO_H3P) {
            *(float2*)(hdst + g2 * 260 + j0)           = make_float2(a0, c0);
            *(float2*)(hdst + (g2 + 1) * 260 + j0)     = make_float2(a1, c1);
            *(float2*)(hdst + g2 * 260 + j0 + 2)       = make_float2(d0, e0);
            *(float2*)(hdst + (g2 + 1) * 260 + j0 + 2) = make_float2(d1, e1);
        } else {
            *(float4*)(hdst + j0 * HSTR + g2 * 2)       = make_float4(a0, a0, a1, a1);
            *(float4*)(hdst + (j0 + 1) * HSTR + g2 * 2) = make_float4(c0, c0, c1, c1);
            *(float4*)(hdst + (j0 + 2) * HSTR + g2 * 2) = make_float4(d0, d0, d1, d1);
            *(float4*)(hdst + (j0 + 3) * HSTR + g2 * 2) = make_float4(e0, e0, e1, e1);
        }
    }
}

__global__ __launch_bounds__(NTHR, 1)
void ode_main(const float* __restrict__ t, const float* __restrict__ x,
              const float* __restrict__ z, const float* __restrict__ event_t,
              const float* __restrict__ z_jump,
              const float* __restrict__ W1, const float* __restrict__ b1,
              const float* __restrict__ W2, const float* __restrict__ b2,
              const float* __restrict__ W3, const float* __restrict__ b3,
              const float* __restrict__ W4, const float* __restrict__ b4,
              float* __restrict__ out)
{
    extern __shared__ float sm[];
    float* w2c  = sm + OFF_W2;
    float* w3c  = sm + OFF_W3;
    float* strb = sm + OFF_STR;
    float* hA   = sm + OFF_HA;
    float* hB   = sm + OFF_HB;
    float* h3p  = sm + OFF_H3;
    float* w4t  = sm + OFF_W4;
    float* inp  = sm + OFF_INP;
    float* red  = sm + OFF_SCR;                 // union: red / araw / reduce-scratch
    u64*   scr64= (u64*)(sm + OFF_SCR);
    float* zjs  = sm + OFF_ZJ;
    float* evts = sm + OFF_EVT;
    float* b4s  = sm + OFF_B4;
    float* tsh  = sm + OFF_TSH;

    const int tid = threadIdx.x;
    const int b0  = blockIdx.x * 8;
    const unsigned str_u32 = (unsigned)__cvta_generic_to_shared(strb);

    // ---- lane decompositions ----
    const int lane = tid & 31, warp = tid >> 5;
    // big layers: j-quad x 8 batches x K-eighth
    const int quad = (warp >> 1) * 8 + (lane & 7);
    const int j0q  = quad * 4;
    const int kq8  = (warp & 1) * 4 + (lane >> 3);
    // layer 1: j-pair x 2 batches
    const int pair = tid & 127;
    const int j0p  = pair * 2;
    const int bg   = tid >> 7;       // 0..3 -> batches 2bg, 2bg+1
    const int gb   = bg * 2;

    // ---- init: SMEM caches + raw inputs ----
    for (int idx = tid; idx < ICC * HH; idx += NTHR) { w2c[idx] = W2[idx]; w3c[idx] = W3[idx]; }
    for (int idx = tid; idx < 8 * HH; idx += NTHR) {
        int k = idx >> 8, i = idx & 255;
        w4t[k * 260 + i] = W4[i * 8 + k];
    }
    if (tid < 8) { evts[tid] = event_t[b0 + tid]; b4s[tid] = b4[tid]; }
    if (tid < 64) { int g = tid >> 3, i = tid & 7; zjs[tid] = z_jump[(b0 + g) * 8 + i]; }
    if (tid == 0) { tsh[0] = t[0]; tsh[1] = t[1]; }

    float zreg = 0.f; size_t zbase = 0;
    if (tid >= 64 && tid < 128) {
        int r = tid - 64, g = r >> 3, i = r & 7;
        zbase = (size_t)(b0 + g) * Tt * 8 + i;
    }
    float treg = 0.f;
    if (tid == 192) treg = t[2];

    if (tid < 64) {
        int k = tid & 7, g = tid >> 3;
        float xv = x[(size_t)(b0 + g) * Tt * 8 + k];
        red[k * 8 + g] = xv;
        inp[k * 16 + g * 2] = xv; inp[k * 16 + g * 2 + 1] = xv;
        out[(size_t)(b0 + g) * Tt * 8 + k] = xv;
    } else if (tid < 128) {
        int r = tid - 64, g = r >> 3, zi = r & 7;
        float z0 = z[zbase];
        red[(8 + zi) * 8 + g] = z0;
        zreg = z[zbase + 8];
    }
    __syncthreads();

    if (tid >= 64 && tid < 128) {
        int r = tid - 64, g = r >> 3, zi = r & 7;
        float v = (tsh[0] >= evts[g]) ? zjs[r] : red[(8 + zi) * 8 + g];
        inp[(8 + zi) * 16 + g * 2] = v; inp[(8 + zi) * 16 + g * 2 + 1] = v;
    }

    // per-thread layer-1 weights + cinit (j-pair x 2 batches)
    u64 wxz[16];
    u64 cig[2];
    {
        float cx = b1[j0p], cy = b1[j0p + 1];
        float ca[2][2];
#pragma unroll
        for (int gp = 0; gp < 2; gp++) { ca[gp][0] = cx; ca[gp][1] = cy; }
#pragma unroll
        for (int i = 0; i < 16; i++) {
            float2 wa = *(const float2*)&W1[i * HH + j0p];
            float2 wb = *(const float2*)&W1[(16 + i) * HH + j0p];
            float2 wc = *(const float2*)&W1[(32 + i) * HH + j0p];
            wxz[i] = pack2(wb.x + wc.x, wb.y + wc.y);
            float dx = wa.x - wb.x, dy = wa.y - wb.y;
#pragma unroll
            for (int gp = 0; gp < 2; gp++) {
                float a = red[i * 8 + gb + gp];
                ca[gp][0] = fmaf(a, dx, ca[gp][0]);
                ca[gp][1] = fmaf(a, dy, ca[gp][1]);
            }
        }
#pragma unroll
        for (int gp = 0; gp < 2; gp++) cig[gp] = pack2(ca[gp][0], ca[gp][1]);
    }
    const ulonglong2 b2q = *(const ulonglong2*)&b2[j0q];
    const ulonglong2 b3q = *(const ulonglong2*)&b3[j0q];

    // layer-4 mapping: 8-way split over K
    const int c4 = tid >> 6, r4 = tid & 63, k4 = r4 & 7, g4 = r4 >> 3;
    __syncthreads();

    for (int s = 0; s < Tt - 1; s++) {
        const float t0 = tsh[s & 1];
        const float t1 = tsh[(s + 1) & 1];
        const float dt = t1 - t0;

        // stream prologue: 3 chunks in flight during layer 1
        issue_chunk(0, str_u32, W2, W3, tid);
        issue_chunk(1, str_u32, W2, W3, tid);
        issue_chunk(2, str_u32, W2, W3, tid);

        // ---- layer 1 (K=16, folded), j-pair x 2 batches ----
        {
            u64 acc[2] = { cig[0], cig[1] };
#pragma unroll
            for (int i = 0; i < 16; i++) {
                ulonglong2 hv = *(const ulonglong2*)(inp + i * 16 + bg * 4);
                acc[0] = ffma2(hv.x, wxz[i], acc[0]);
                acc[1] = ffma2(hv.y, wxz[i], acc[1]);
            }
#pragma unroll
            for (int gp = 0; gp < 2; gp++) {
                float2 v = unpack2(acc[gp]);
                v.x = elu1(v.x); v.y = elu1(v.y);
                int g = gb + gp;
                *(u64*)(hA + j0p * HSTR + g * 2)       = pack2(v.x, v.x);
                *(u64*)(hA + (j0p + 1) * HSTR + g * 2) = pack2(v.y, v.y);
            }
        }
        __syncthreads();

        // t rolling slot + z prefetch for step s+2
        if (tid == 192) {
            if (s + 2 < Tt) tsh[s & 1] = treg;
            if (s + 3 < Tt) treg = t[s + 3];
        }
        float znext = 0.f;
        if (tid >= 64 && tid < 128 && s + 2 < Tt) znext = z[zbase + (size_t)(s + 2) * 8];

        // ---- layer 2 ----
        biglayerB<false>(w2c, strb, W2, W3, hA, hB, scr64,
                         j0q, kq8, quad, 0, b2q, str_u32, tid, warp, lane);
        __syncthreads();

        // ---- layer 3 ----
        biglayerB<true>(w3c, strb, W2, W3, hB, h3p, scr64,
                        j0q, kq8, quad, 1, b3q, str_u32, tid, warp, lane);
        __syncthreads();

        // ---- layer 4 partials (8-way K split) ----
        {
            float p = 0.f;
            const int base = c4 * 32;
            const float* hp = h3p + g4 * 260 + base;
            const float* wp = w4t + k4 * 260 + base;
#pragma unroll
            for (int it = 0; it < 8; it++) {
                float4 hv = *(const float4*)(hp + it * 4);
                float4 wv = *(const float4*)(wp + it * 4);
                p = fmaf(hv.x, wv.x, p); p = fmaf(hv.y, wv.y, p);
                p = fmaf(hv.z, wv.z, p); p = fmaf(hv.w, wv.w, p);
            }
            red[tid] = p;
        }
        __syncthreads();

        // ---- epilogue ----
        if (tid < 64) {
            int k = tid & 7, g = tid >> 3;
            float o = b4s[k];
#pragma unroll
            for (int m = 0; m < 8; m++) o += red[tid + 64 * m];
            float xn = inp[k * 16 + g * 2] + dt * o;
            inp[k * 16 + g * 2] = xn; inp[k * 16 + g * 2 + 1] = xn;
            out[(size_t)(b0 + g) * Tt * 8 + (size_t)(s + 1) * 8 + k] = xn;
        } else if (tid < 128) {
            int r = tid - 64, g = r >> 3, zi = r & 7;
            float v = (t1 >= evts[g]) ? zjs[r] : zreg;
            inp[(8 + zi) * 16 + g * 2] = v; inp[(8 + zi) * 16 + g * 2 + 1] = v;
            zreg = znext;
        }
        __syncthreads();
    }
}

extern "C" void kernel_launch(void* const* d_in, const int* in_sizes, int n_in,
                              void* d_out, int out_size) {
    const float* t       = (const float*)d_in[0];
    const float* x       = (const float*)d_in[1];
    const float* z       = (const float*)d_in[2];
    const float* event_t = (const float*)d_in[3];
    const float* z_jump  = (const float*)d_in[4];
    const float* W1      = (const float*)d_in[5];
    const float* b1      = (const float*)d_in[6];
    const float* W2      = (const float*)d_in[7];
    const float* b2      = (const float*)d_in[8];
    const float* W3      = (const float*)d_in[9];
    const float* b3      = (const float*)d_in[10];
    const float* W4      = (const float*)d_in[11];
    const float* b4      = (const float*)d_in[12];
    float* out = (float*)d_out;

    cudaFuncSetAttribute(ode_main, cudaFuncAttributeMaxDynamicSharedMemorySize, SM_BYTES);

    ode_main<<<NBLK, NTHR, SM_BYTES>>>(t, x, z, event_t, z_jump,
                                       W1, b1, W2, b2, W3, b3, W4, b4, out);
}

// round 9
// speedup vs baseline: 1.3995x; 1.3995x over previous
#include <cuda_runtime.h>
#include <cstdint>

#define Bt    1024
#define Tt    1000
#define HH    256
#define NBLK  128
#define NTHR  256
#define ICC   32              // W2/W3 rows resident in SMEM (8 iterations of 4)
#define CHROWS 16             // rows per streamed chunk
#define NCHL  14              // chunks per layer: (256-32)/16
#define NGRP  7               // pair-groups per layer
#define NGTOT 14              // total groups (2 layers)
#define NSTG  6               // SMEM stages (3 pair-groups resident)
#define HSTR  20              // dup-activation row stride (conflict-free)

using u64 = unsigned long long;

__device__ __forceinline__ u64 ffma2(u64 a, u64 b, u64 c) {
    u64 d; asm("fma.rn.f32x2 %0,%1,%2,%3;" : "=l"(d) : "l"(a), "l"(b), "l"(c)); return d;
}
__device__ __forceinline__ u64 addf2(u64 a, u64 b) {
    u64 d; asm("add.rn.f32x2 %0,%1,%2;" : "=l"(d) : "l"(a), "l"(b)); return d;
}
__device__ __forceinline__ u64 pack2(float x, float y) {
    u64 d; asm("mov.b64 %0,{%1,%2};" : "=l"(d) : "f"(x), "f"(y)); return d;
}
__device__ __forceinline__ float2 unpack2(u64 a) {
    float2 f; asm("mov.b64 {%0,%1},%2;" : "=f"(f.x), "=f"(f.y) : "l"(a)); return f;
}
__device__ __forceinline__ float elu1(float v) { return v > 0.f ? v : (__expf(v) - 1.f); }

// ---------------- SMEM layout (float offsets) ----------------
#define OFF_W2   0                      // 32*256 = 8192
#define OFF_W3   8192                   // 8192
#define OFF_STR  16384                  // 6*16*256 = 24576
#define OFF_HA   40960                  // 256*20 = 5120 (dup, padded)
#define OFF_HB   46080                  // 5120
#define OFF_H3   51200                  // 8*260 = 2080
#define OFF_W4   53280                  // 8*260 = 2080
#define OFF_INP  55360                  // 16*16 = 256 (dup, stride 16)
#define OFF_RED  55616                  // 256 (also araw scratch)
#define OFF_ZJ   55872                  // 64
#define OFF_EVT  55936                  // 8
#define OFF_B4   55944                  // 8
#define OFF_TSH  55952                  // 2
#define SM_FLOATS 55954
#define SM_BYTES  (SM_FLOATS * 4)       // 223816 B (< 232448 cap)

#define STG_FLOATS (CHROWS * HH)        // 4096

// one weight-row accumulation: acc{0,1}[g] += h[g] * (w pair); h rows stride HSTR
__device__ __forceinline__ void accum_iter(const float* __restrict__ wrow_j0,
                                           const float* __restrict__ hrow,
                                           u64* __restrict__ acc0, u64* __restrict__ acc1) {
    ulonglong2 w = *(const ulonglong2*)wrow_j0;   // (w_j0,w_j1),(w_j2,w_j3)
    u64 hv[8];
    *(ulonglong2*)&hv[0] = *(const ulonglong2*)(hrow);
    *(ulonglong2*)&hv[2] = *(const ulonglong2*)(hrow + 4);
    *(ulonglong2*)&hv[4] = *(const ulonglong2*)(hrow + 8);
    *(ulonglong2*)&hv[6] = *(const ulonglong2*)(hrow + 12);
#pragma unroll
    for (int g = 0; g < 8; g++) {
        acc0[g] = ffma2(hv[g], w.x, acc0[g]);
        acc1[g] = ffma2(hv[g], w.y, acc1[g]);
    }
}

// issue one pair-group (2 chunks of 16 rows) as a single commit group
__device__ __forceinline__ void issue_group(int g, unsigned str_u32,
                                            const float* __restrict__ W2,
                                            const float* __restrict__ W3, int tid) {
    if (g >= NGTOT) return;
#pragma unroll
    for (int h = 0; h < 2; h++) {
        const int k = g * 2 + h;                        // global chunk 0..27
        const int kl = (k < NCHL) ? k : (k - NCHL);
        const char* src = (const char*)((k < NCHL ? W2 : W3) + (ICC + kl * CHROWS) * HH);
        unsigned dst = str_u32 + (unsigned)(k % NSTG) * (STG_FLOATS * 4);
#pragma unroll
        for (int r = 0; r < 4; r++) {
            unsigned off = (unsigned)(tid + r * NTHR) * 16;
            asm volatile("cp.async.cg.shared.global [%0], [%1], 16;" :: "r"(dst + off), "l"(src + off));
        }
    }
    asm volatile("cp.async.commit_group;");
}

// full 256->256 layer: K-quarter partials + shuffle reduction + bias + ELU + writeback
template <bool TO_H3P>
__device__ __forceinline__ void biglayerA(
    const float* __restrict__ wc, const float* __restrict__ strb,
    const float* __restrict__ W2, const float* __restrict__ W3,
    const float* __restrict__ hsrc, float* __restrict__ hdst,
    int j0, int kq, int ga, int layer, ulonglong2 bq,
    unsigned str_u32, int tid)
{
    u64 acc0[8], acc1[8];
#pragma unroll
    for (int g = 0; g < 8; g++) { acc0[g] = 0ull; acc1[g] = 0ull; }

    // cached rows: iterations n, this lane handles row 4n+kq
#pragma unroll
    for (int n = 0; n < ICC / 4; n++) {
        int i = n * 4 + kq;
        accum_iter(wc + i * HH + j0, hsrc + i * HSTR, acc0, acc1);
    }
    // streamed pair-groups: 7 per layer, 8 accum iterations each
#pragma unroll 1
    for (int gp = 0; gp < NGRP; gp++) {
        const int g = layer * NGRP + gp;
        if (g < NGTOT - 1) asm volatile("cp.async.wait_group 1;" ::: "memory");
        else               asm volatile("cp.async.wait_group 0;" ::: "memory");
        __syncthreads();
        issue_group(g + 2, str_u32, W2, W3, tid);
#pragma unroll
        for (int h = 0; h < 2; h++) {
            const int k = g * 2 + h;
            const float* sb = strb + (k % NSTG) * STG_FLOATS;
            const int base = ICC + (gp * 2 + h) * CHROWS;
#pragma unroll
            for (int m = 0; m < 4; m++) {
                int io = m * 4 + kq;
                accum_iter(sb + io * HH + j0, hsrc + (base + io) * HSTR, acc0, acc1);
            }
        }
    }

    // K-reduction across kq via shuffles (lanes ^8, ^16)
#pragma unroll
    for (int g = 0; g < 8; g++) {
        acc0[g] = addf2(acc0[g], __shfl_xor_sync(0xffffffffu, acc0[g], 8));
        acc0[g] = addf2(acc0[g], __shfl_xor_sync(0xffffffffu, acc0[g], 16));
        acc1[g] = addf2(acc1[g], __shfl_xor_sync(0xffffffffu, acc1[g], 8));
        acc1[g] = addf2(acc1[g], __shfl_xor_sync(0xffffffffu, acc1[g], 16));
    }

    // each lane finalizes its 2-batch slice (ga, ga+1) for j0..j0+3
    float2 bp  = unpack2(bq.x);   // bias (j0, j0+1)
    float2 bp2 = unpack2(bq.y);   // bias (j0+2, j0+3)
    float2 va = unpack2(acc0[ga]), vb = unpack2(acc0[ga + 1]);
    float a0 = elu1(va.x + bp.x),  a1 = elu1(vb.x + bp.x);    // j0   : g=ga, ga+1
    float c0 = elu1(va.y + bp.y),  c1 = elu1(vb.y + bp.y);    // j0+1
    float2 vc = unpack2(acc1[ga]), vd = unpack2(acc1[ga + 1]);
    float d0 = elu1(vc.x + bp2.x), d1 = elu1(vd.x + bp2.x);   // j0+2
    float e0 = elu1(vc.y + bp2.y), e1 = elu1(vd.y + bp2.y);   // j0+3

    if (TO_H3P) {
        *(float2*)(hdst + ga * 260 + j0)           = make_float2(a0, c0);
        *(float2*)(hdst + (ga + 1) * 260 + j0)     = make_float2(a1, c1);
        *(float2*)(hdst + ga * 260 + j0 + 2)       = make_float2(d0, e0);
        *(float2*)(hdst + (ga + 1) * 260 + j0 + 2) = make_float2(d1, e1);
    } else {
        *(float4*)(hdst + j0 * HSTR + ga * 2)       = make_float4(a0, a0, a1, a1);
        *(float4*)(hdst + (j0 + 1) * HSTR + ga * 2) = make_float4(c0, c0, c1, c1);
        *(float4*)(hdst + (j0 + 2) * HSTR + ga * 2) = make_float4(d0, d0, d1, d1);
        *(float4*)(hdst + (j0 + 3) * HSTR + ga * 2) = make_float4(e0, e0, e1, e1);
    }
}

__global__ __launch_bounds__(NTHR, 1)
void ode_main(const float* __restrict__ t, const float* __restrict__ x,
              const float* __restrict__ z, const float* __restrict__ event_t,
              const float* __restrict__ z_jump,
              const float* __restrict__ W1, const float* __restrict__ b1,
              const float* __restrict__ W2, const float* __restrict__ b2,
              const float* __restrict__ W3, const float* __restrict__ b3,
              const float* __restrict__ W4, const float* __restrict__ b4,
              float* __restrict__ out)
{
    extern __shared__ float sm[];
    float* w2c  = sm + OFF_W2;
    float* w3c  = sm + OFF_W3;
    float* strb = sm + OFF_STR;
    float* hA   = sm + OFF_HA;
    float* hB   = sm + OFF_HB;
    float* h3p  = sm + OFF_H3;
    float* w4t  = sm + OFF_W4;
    float* inp  = sm + OFF_INP;
    float* red  = sm + OFF_RED;
    float* zjs  = sm + OFF_ZJ;
    float* evts = sm + OFF_EVT;
    float* b4s  = sm + OFF_B4;
    float* tsh  = sm + OFF_TSH;

    const int tid = threadIdx.x;
    const int b0  = blockIdx.x * 8;
    const unsigned str_u32 = (unsigned)__cvta_generic_to_shared(strb);

    // ---- lane decompositions ----
    const int lane = tid & 31, warp = tid >> 5;
    // big layers: j-quad x 8 batches x K-quarter
    const int quad = warp * 8 + (lane & 7);
    const int j0q  = quad * 4;
    const int kq   = lane >> 3;
    const int ga   = kq * 2;
    // layer 1: j-pair x 4 batches
    const int j0  = warp * 32 + (lane & 15) * 2;
    const int gq  = lane >> 4;
    const int gq8 = gq * 8;

    // ---- init: SMEM caches + raw inputs ----
    for (int idx = tid; idx < ICC * HH; idx += NTHR) { w2c[idx] = W2[idx]; w3c[idx] = W3[idx]; }
    for (int idx = tid; idx < 8 * HH; idx += NTHR) {
        int k = idx >> 8, i = idx & 255;
        w4t[k * 260 + i] = W4[i * 8 + k];
    }
    if (tid < 8) { evts[tid] = event_t[b0 + tid]; b4s[tid] = b4[tid]; }
    if (tid < 64) { int g = tid >> 3, i = tid & 7; zjs[tid] = z_jump[(b0 + g) * 8 + i]; }
    if (tid == 0) { tsh[0] = t[0]; tsh[1] = t[1]; }

    float zreg = 0.f; size_t zbase = 0;
    if (tid >= 64 && tid < 128) {
        int r = tid - 64, g = r >> 3, i = r & 7;
        zbase = (size_t)(b0 + g) * Tt * 8 + i;
    }
    float treg = 0.f;
    if (tid == 192) treg = t[2];

    if (tid < 64) {
        int k = tid & 7, g = tid >> 3;
        float xv = x[(size_t)(b0 + g) * Tt * 8 + k];
        red[k * 8 + g] = xv;
        inp[k * 16 + g * 2] = xv; inp[k * 16 + g * 2 + 1] = xv;
        out[(size_t)(b0 + g) * Tt * 8 + k] = xv;
    } else if (tid < 128) {
        int r = tid - 64, g = r >> 3, zi = r & 7;
        float z0 = z[zbase];
        red[(8 + zi) * 8 + g] = z0;
        zreg = z[zbase + 8];
    }
    __syncthreads();

    if (tid >= 64 && tid < 128) {
        int r = tid - 64, g = r >> 3, zi = r & 7;
        float v = (tsh[0] >= evts[g]) ? zjs[r] : red[(8 + zi) * 8 + g];
        inp[(8 + zi) * 16 + g * 2] = v; inp[(8 + zi) * 16 + g * 2 + 1] = v;
    }

    // per-thread layer-1 weights + cinit
    u64 wxz[16];
    u64 cig[4];
    {
        float c0 = b1[j0], c1 = b1[j0 + 1];
        float ca[4][2];
#pragma unroll
        for (int gp = 0; gp < 4; gp++) { ca[gp][0] = c0; ca[gp][1] = c1; }
#pragma unroll
        for (int i = 0; i < 16; i++) {
            float2 wa = *(const float2*)&W1[i * HH + j0];
            float2 wb = *(const float2*)&W1[(16 + i) * HH + j0];
            float2 wc = *(const float2*)&W1[(32 + i) * HH + j0];
            wxz[i] = pack2(wb.x + wc.x, wb.y + wc.y);
            float dx = wa.x - wb.x, dy = wa.y - wb.y;
#pragma unroll
            for (int gp = 0; gp < 4; gp++) {
                float a = red[i * 8 + gq * 4 + gp];
                ca[gp][0] = fmaf(a, dx, ca[gp][0]);
                ca[gp][1] = fmaf(a, dy, ca[gp][1]);
            }
        }
#pragma unroll
        for (int gp = 0; gp < 4; gp++) cig[gp] = pack2(ca[gp][0], ca[gp][1]);
    }
    const ulonglong2 b2q = *(const ulonglong2*)&b2[j0q];
    const ulonglong2 b3q = *(const ulonglong2*)&b3[j0q];

    const int c4 = tid >> 6, r4 = tid & 63, k4 = r4 & 7, g4 = r4 >> 3;
    __syncthreads();

    for (int s = 0; s < Tt - 1; s++) {
        const float t0 = tsh[s & 1];
        const float t1 = tsh[(s + 1) & 1];
        const float dt = t1 - t0;

        // stream prologue: 2 pair-groups (4 chunks) in flight during layer 1
        issue_group(0, str_u32, W2, W3, tid);
        issue_group(1, str_u32, W2, W3, tid);

        // ---- layer 1 (K=16, folded) ----
        {
            u64 acc[4] = { cig[0], cig[1], cig[2], cig[3] };
#pragma unroll
            for (int i = 0; i < 16; i++) {
                const float* hr = inp + i * 16 + gq8;
                ulonglong2 h01 = *(const ulonglong2*)(hr);
                ulonglong2 h23 = *(const ulonglong2*)(hr + 4);
                acc[0] = ffma2(h01.x, wxz[i], acc[0]);
                acc[1] = ffma2(h01.y, wxz[i], acc[1]);
                acc[2] = ffma2(h23.x, wxz[i], acc[2]);
                acc[3] = ffma2(h23.y, wxz[i], acc[3]);
            }
#pragma unroll
            for (int gp = 0; gp < 4; gp++) {
                float2 v = unpack2(acc[gp]);
                v.x = elu1(v.x); v.y = elu1(v.y);
                int g = gq * 4 + gp;
                *(u64*)(hA + j0 * HSTR + g * 2)       = pack2(v.x, v.x);
                *(u64*)(hA + (j0 + 1) * HSTR + g * 2) = pack2(v.y, v.y);
            }
        }
        __syncthreads();

        // t rolling slot + z prefetch for step s+2
        if (tid == 192) {
            if (s + 2 < Tt) tsh[s & 1] = treg;
            if (s + 3 < Tt) treg = t[s + 3];
        }
        float znext = 0.f;
        if (tid >= 64 && tid < 128 && s + 2 < Tt) znext = z[zbase + (size_t)(s + 2) * 8];

        // ---- layer 2 ----
        biglayerA<false>(w2c, strb, W2, W3, hA, hB, j0q, kq, ga, 0, b2q, str_u32, tid);
        __syncthreads();

        // ---- layer 3 ----
        biglayerA<true>(w3c, strb, W2, W3, hB, h3p, j0q, kq, ga, 1, b3q, str_u32, tid);
        __syncthreads();

        // ---- layer 4 partials ----
        {
            float p = 0.f;
            const int base = c4 * 64;
            const float* hp = h3p + g4 * 260 + base;
            const float* wp = w4t + k4 * 260 + base;
#pragma unroll
            for (int it = 0; it < 16; it++) {
                float4 hv = *(const float4*)(hp + it * 4);
                float4 wv = *(const float4*)(wp + it * 4);
                p = fmaf(hv.x, wv.x, p); p = fmaf(hv.y, wv.y, p);
                p = fmaf(hv.z, wv.z, p); p = fmaf(hv.w, wv.w, p);
            }
            red[tid] = p;
        }
        __syncthreads();

        // ---- epilogue ----
        if (tid < 64) {
            int k = tid & 7, g = tid >> 3;
            float o = b4s[k] + red[tid] + red[tid + 64] + red[tid + 128] + red[tid + 192];
            float xn = inp[k * 16 + g * 2] + dt * o;
            inp[k * 16 + g * 2] = xn; inp[k * 16 + g * 2 + 1] = xn;
            out[(size_t)(b0 + g) * Tt * 8 + (size_t)(s + 1) * 8 + k] = xn;
        } else if (tid < 128) {
            int r = tid - 64, g = r >> 3, zi = r & 7;
            float v = (t1 >= evts[g]) ? zjs[r] : zreg;
            inp[(8 + zi) * 16 + g * 2] = v; inp[(8 + zi) * 16 + g * 2 + 1] = v;
            zreg = znext;
        }
        __syncthreads();
    }
}

extern "C" void kernel_launch(void* const* d_in, const int* in_sizes, int n_in,
                              void* d_out, int out_size) {
    const float* t       = (const float*)d_in[0];
    const float* x       = (const float*)d_in[1];
    const float* z       = (const float*)d_in[2];
    const float* event_t = (const float*)d_in[3];
    const float* z_jump  = (const float*)d_in[4];
    const float* W1      = (const float*)d_in[5];
    const float* b1      = (const float*)d_in[6];
    const float* W2      = (const float*)d_in[7];
    const float* b2      = (const float*)d_in[8];
    const float* W3      = (const float*)d_in[9];
    const float* b3      = (const float*)d_in[10];
    const float* W4      = (const float*)d_in[11];
    const float* b4      = (const float*)d_in[12];
    float* out = (float*)d_out;

    cudaFuncSetAttribute(ode_main, cudaFuncAttributeMaxDynamicSharedMemorySize, SM_BYTES);

    ode_main<<<NBLK, NTHR, SM_BYTES>>>(t, x, z, event_t, z_jump,
                                       W1, b1, W2, b2, W3, b3, W4, b4, out);
}

// round 10
// speedup vs baseline: 1.5607x; 1.1151x over previous
#include <cuda_runtime.h>
#include <cstdint>

#define Bt    1024
#define Tt    1000
#define HH    256
#define NBLK  128
#define NTHR  256
#define ICC   32              // W2/W3 rows resident in SMEM
#define CHROWS 16             // rows per streamed chunk
#define NCHL  14              // chunks per layer: (256-32)/16
#define NGRP  7               // pair-groups per layer
#define NGTOT 14              // total groups (2 layers)
#define NSTG  6               // SMEM stages (3 pair-groups resident)

// non-dup activation row: 8 floats + 16B pad per 4 rows; HROW(4n+kq)=36n+8kq
#define HBUF  2304            // floats per activation buffer (256 rows)

using u64 = unsigned long long;

__device__ __forceinline__ u64 ffma2(u64 a, u64 b, u64 c) {
    u64 d; asm("fma.rn.f32x2 %0,%1,%2,%3;" : "=l"(d) : "l"(a), "l"(b), "l"(c)); return d;
}
__device__ __forceinline__ u64 addf2(u64 a, u64 b) {
    u64 d; asm("add.rn.f32x2 %0,%1,%2;" : "=l"(d) : "l"(a), "l"(b)); return d;
}
__device__ __forceinline__ u64 pack2(float x, float y) {
    u64 d; asm("mov.b64 %0,{%1,%2};" : "=l"(d) : "f"(x), "f"(y)); return d;
}
__device__ __forceinline__ float2 unpack2(u64 a) {
    float2 f; asm("mov.b64 {%0,%1},%2;" : "=f"(f.x), "=f"(f.y) : "l"(a)); return f;
}
__device__ __forceinline__ float elu1(float v) { return v > 0.f ? v : (__expf(v) - 1.f); }

// ---------------- SMEM layout (float offsets) ----------------
#define OFF_W2   0                      // 32*256 = 8192
#define OFF_W3   8192                   // 8192
#define OFF_STR  16384                  // 6*16*256 = 24576
#define OFF_HA   40960                  // 2304
#define OFF_HB   43264                  // 2304
#define OFF_H3   45568                  // 8*260 = 2080
#define OFF_W4   47648                  // 8*260 = 2080
#define OFF_INP  49728                  // 144 (16 rows, HROW layout)
#define OFF_RED  49872                  // 256 (also araw scratch)
#define OFF_ZJ   50128                  // 64
#define OFF_EVT  50192                  // 8
#define OFF_B4   50200                  // 8
#define OFF_TSH  50208                  // 2
#define SM_FLOATS 50210
#define SM_BYTES  (SM_FLOATS * 4)       // 200840 B

#define STG_FLOATS (CHROWS * HH)        // 4096

// one weight-row accumulation (reg-dup weights, non-dup h):
// acc[jj*4+gp] += dup(w_jj) * (h_{2gp}, h_{2gp+1})
__device__ __forceinline__ void accum_iter(const float* __restrict__ w16,
                                           const float* __restrict__ h8,
                                           u64* __restrict__ acc) {
    ulonglong2 w = *(const ulonglong2*)w16;          // w_j0..j3
    float2 wl = unpack2(w.x), wh = unpack2(w.y);
    u64 wd0 = pack2(wl.x, wl.x), wd1 = pack2(wl.y, wl.y);
    u64 wd2 = pack2(wh.x, wh.x), wd3 = pack2(wh.y, wh.y);
    ulonglong2 hlo = *(const ulonglong2*)h8;         // (g0,g1),(g2,g3)
    ulonglong2 hhi = *(const ulonglong2*)(h8 + 4);   // (g4,g5),(g6,g7)
    acc[0]  = ffma2(hlo.x, wd0, acc[0]);  acc[1]  = ffma2(hlo.y, wd0, acc[1]);
    acc[2]  = ffma2(hhi.x, wd0, acc[2]);  acc[3]  = ffma2(hhi.y, wd0, acc[3]);
    acc[4]  = ffma2(hlo.x, wd1, acc[4]);  acc[5]  = ffma2(hlo.y, wd1, acc[5]);
    acc[6]  = ffma2(hhi.x, wd1, acc[6]);  acc[7]  = ffma2(hhi.y, wd1, acc[7]);
    acc[8]  = ffma2(hlo.x, wd2, acc[8]);  acc[9]  = ffma2(hlo.y, wd2, acc[9]);
    acc[10] = ffma2(hhi.x, wd2, acc[10]); acc[11] = ffma2(hhi.y, wd2, acc[11]);
    acc[12] = ffma2(hlo.x, wd3, acc[12]); acc[13] = ffma2(hlo.y, wd3, acc[13]);
    acc[14] = ffma2(hhi.x, wd3, acc[14]); acc[15] = ffma2(hhi.y, wd3, acc[15]);
}

// issue one pair-group (2 chunks of 16 rows) as a single commit group
__device__ __forceinline__ void issue_group(int g, unsigned str_u32,
                                            const float* __restrict__ W2,
                                            const float* __restrict__ W3, int tid) {
    if (g >= NGTOT) return;
#pragma unroll
    for (int h = 0; h < 2; h++) {
        const int k = g * 2 + h;
        const int kl = (k < NCHL) ? k : (k - NCHL);
        const char* src = (const char*)((k < NCHL ? W2 : W3) + (ICC + kl * CHROWS) * HH);
        unsigned dst = str_u32 + (unsigned)(k % NSTG) * (STG_FLOATS * 4);
#pragma unroll
        for (int r = 0; r < 4; r++) {
            unsigned off = (unsigned)(tid + r * NTHR) * 16;
            asm volatile("cp.async.cg.shared.global [%0], [%1], 16;" :: "r"(dst + off), "l"(src + off));
        }
    }
    asm volatile("cp.async.commit_group;");
}

// full 256->256 layer: K-quarter partials + shuffle reduction + bias + ELU + writeback
template <bool TO_H3P>
__device__ __forceinline__ void biglayerA(
    const float* __restrict__ wc, const float* __restrict__ strb,
    const float* __restrict__ W2, const float* __restrict__ W3,
    const float* __restrict__ hsrc, float* __restrict__ hdst,
    int j0q, int kq, int quadg, int layer, ulonglong2 bq,
    unsigned str_u32, int tid)
{
    u64 acc[16];
#pragma unroll
    for (int q = 0; q < 16; q++) acc[q] = 0ull;

    const float* wt = wc + kq * HH + j0q;     // cached-weight lane base
    const float* ht = hsrc + kq * 8;          // h lane base: HROW(4n+kq)=36n+8kq

    // cached rows: n = 0..7 (row 4n+kq)
#pragma unroll
    for (int n = 0; n < ICC / 4; n++)
        accum_iter(wt + n * 4 * HH, ht + n * 36, acc);

    // streamed pair-groups: 7 per layer, 8 accum iterations each
#pragma unroll 1
    for (int gp = 0; gp < NGRP; gp++) {
        const int g = layer * NGRP + gp;
        if (g < NGTOT - 1) asm volatile("cp.async.wait_group 1;" ::: "memory");
        else               asm volatile("cp.async.wait_group 0;" ::: "memory");
        __syncthreads();
        issue_group(g + 2, str_u32, W2, W3, tid);
#pragma unroll
        for (int h = 0; h < 2; h++) {
            const int k = g * 2 + h;
            const float* sb = strb + (k % NSTG) * STG_FLOATS + kq * HH + j0q;
            const int nbase = ICC / 4 + (gp * 2 + h) * 4;      // global n for h rows
#pragma unroll
            for (int m = 0; m < 4; m++)
                accum_iter(sb + m * 4 * HH, ht + (nbase + m) * 36, acc);
        }
    }

    // K-reduction across kq via shuffles (lanes ^8, ^16)
#pragma unroll
    for (int q = 0; q < 16; q++) {
        acc[q] = addf2(acc[q], __shfl_xor_sync(0xffffffffu, acc[q], 8));
        acc[q] = addf2(acc[q], __shfl_xor_sync(0xffffffffu, acc[q], 16));
    }

    // lane finalizes g-pair gp = kq for its 4 j's
    float2 blo = unpack2(bq.x), bhi = unpack2(bq.y);
    const float bj[4] = { blo.x, blo.y, bhi.x, bhi.y };
    float vx[4], vy[4];
#pragma unroll
    for (int jj = 0; jj < 4; jj++) {
        float2 v = unpack2(acc[jj * 4 + kq]);
        vx[jj] = elu1(v.x + bj[jj]);
        vy[jj] = elu1(v.y + bj[jj]);
    }

    if (TO_H3P) {
        *(float4*)(hdst + (2 * kq) * 260 + j0q)     = make_float4(vx[0], vx[1], vx[2], vx[3]);
        *(float4*)(hdst + (2 * kq + 1) * 260 + j0q) = make_float4(vy[0], vy[1], vy[2], vy[3]);
    } else {
        float* wb = hdst + 36 * quadg + 2 * kq;   // HROW(4*quadg+jj) = 36*quadg + 8*jj
#pragma unroll
        for (int jj = 0; jj < 4; jj++)
            *(u64*)(wb + 8 * jj) = pack2(vx[jj], vy[jj]);
    }
}

#define INROW(i) ((i) * 8 + ((i) >> 2) * 4)

__global__ __launch_bounds__(NTHR, 1)
void ode_main(const float* __restrict__ t, const float* __restrict__ x,
              const float* __restrict__ z, const float* __restrict__ event_t,
              const float* __restrict__ z_jump,
              const float* __restrict__ W1, const float* __restrict__ b1,
              const float* __restrict__ W2, const float* __restrict__ b2,
              const float* __restrict__ W3, const float* __restrict__ b3,
              const float* __restrict__ W4, const float* __restrict__ b4,
              float* __restrict__ out)
{
    extern __shared__ float sm[];
    float* w2c  = sm + OFF_W2;
    float* w3c  = sm + OFF_W3;
    float* strb = sm + OFF_STR;
    float* hA   = sm + OFF_HA;
    float* hB   = sm + OFF_HB;
    float* h3p  = sm + OFF_H3;
    float* w4t  = sm + OFF_W4;
    float* inp  = sm + OFF_INP;
    float* red  = sm + OFF_RED;
    float* zjs  = sm + OFF_ZJ;
    float* evts = sm + OFF_EVT;
    float* b4s  = sm + OFF_B4;
    float* tsh  = sm + OFF_TSH;

    const int tid = threadIdx.x;
    const int b0  = blockIdx.x * 8;
    const unsigned str_u32 = (unsigned)__cvta_generic_to_shared(strb);

    // ---- lane decompositions ----
    const int lane = tid & 31, warp = tid >> 5;
    // big layers: j-quad x 8 batches x K-quarter
    const int quadg = warp * 8 + (lane & 7);
    const int j0q   = quadg * 4;
    const int kq    = lane >> 3;
    // layer 1: j-pair x 4 batches
    const int pr  = warp * 16 + (lane & 15);   // pair index 0..127
    const int j0  = pr * 2;
    const int gq  = lane >> 4;                 // batch half
    const int l1w = 16 * pr + ((pr >> 1) * 4); // HROW(2*pr)

    // ---- init: SMEM caches + raw inputs ----
    for (int idx = tid; idx < ICC * HH; idx += NTHR) { w2c[idx] = W2[idx]; w3c[idx] = W3[idx]; }
    for (int idx = tid; idx < 8 * HH; idx += NTHR) {
        int k = idx >> 8, i = idx & 255;
        w4t[k * 260 + i] = W4[i * 8 + k];
    }
    if (tid < 8) { evts[tid] = event_t[b0 + tid]; b4s[tid] = b4[tid]; }
    if (tid < 64) { int g = tid >> 3, i = tid & 7; zjs[tid] = z_jump[(b0 + g) * 8 + i]; }
    if (tid == 0) { tsh[0] = t[0]; tsh[1] = t[1]; }

    float zreg = 0.f; size_t zbase = 0;
    if (tid >= 64 && tid < 128) {
        int r = tid - 64, g = r >> 3, i = r & 7;
        zbase = (size_t)(b0 + g) * Tt * 8 + i;
    }
    float treg = 0.f;
    if (tid == 192) treg = t[2];

    if (tid < 64) {
        int k = tid & 7, g = tid >> 3;
        float xv = x[(size_t)(b0 + g) * Tt * 8 + k];
        red[k * 8 + g] = xv;
        inp[INROW(k) + g] = xv;
        out[(size_t)(b0 + g) * Tt * 8 + k] = xv;
    } else if (tid < 128) {
        int r = tid - 64, g = r >> 3, zi = r & 7;
        float z0 = z[zbase];
        red[(8 + zi) * 8 + g] = z0;
        zreg = z[zbase + 8];
    }
    __syncthreads();

    if (tid >= 64 && tid < 128) {
        int r = tid - 64, g = r >> 3, zi = r & 7;
        float v = (tsh[0] >= evts[g]) ? zjs[r] : red[(8 + zi) * 8 + g];
        inp[INROW(8 + zi) + g] = v;
    }

    // per-thread layer-1 weights + cinit  (j-pair x 4 batches, g-pair packed)
    u64 wxz[16];
    u64 cig[4];     // cig[j*2+p] = (c_{j,g0+2p}, c_{j,g0+2p+1})
    {
        float ca[2][4];
        float cx = b1[j0], cy = b1[j0 + 1];
#pragma unroll
        for (int gp = 0; gp < 4; gp++) { ca[0][gp] = cx; ca[1][gp] = cy; }
#pragma unroll
        for (int i = 0; i < 16; i++) {
            float2 wa = *(const float2*)&W1[i * HH + j0];
            float2 wb = *(const float2*)&W1[(16 + i) * HH + j0];
            float2 wc = *(const float2*)&W1[(32 + i) * HH + j0];
            wxz[i] = pack2(wb.x + wc.x, wb.y + wc.y);
            float dx = wa.x - wb.x, dy = wa.y - wb.y;
#pragma unroll
            for (int gp = 0; gp < 4; gp++) {
                float a = red[i * 8 + gq * 4 + gp];
                ca[0][gp] = fmaf(a, dx, ca[0][gp]);
                ca[1][gp] = fmaf(a, dy, ca[1][gp]);
            }
        }
#pragma unroll
        for (int j = 0; j < 2; j++)
#pragma unroll
            for (int p = 0; p < 2; p++)
                cig[j * 2 + p] = pack2(ca[j][2 * p], ca[j][2 * p + 1]);
    }
    const ulonglong2 b2q = *(const ulonglong2*)&b2[j0q];
    const ulonglong2 b3q = *(const ulonglong2*)&b3[j0q];

    const int c4 = tid >> 6, r4 = tid & 63, k4 = r4 & 7, g4 = r4 >> 3;
    __syncthreads();

    for (int s = 0; s < Tt - 1; s++) {
        const float t0 = tsh[s & 1];
        const float t1 = tsh[(s + 1) & 1];
        const float dt = t1 - t0;

        // stream prologue: 2 pair-groups in flight during layer 1
        issue_group(0, str_u32, W2, W3, tid);
        issue_group(1, str_u32, W2, W3, tid);

        // ---- layer 1 (K=16, folded): acc[j][gp] += dup(wxz_j) * (h_g,h_g+1) ----
        {
            u64 acc[4] = { cig[0], cig[1], cig[2], cig[3] };
#pragma unroll
            for (int i = 0; i < 16; i++) {
                ulonglong2 hv = *(const ulonglong2*)(inp + INROW(i) + gq * 4);
                float2 wp = unpack2(wxz[i]);
                u64 wd0 = pack2(wp.x, wp.x), wd1 = pack2(wp.y, wp.y);
                acc[0] = ffma2(hv.x, wd0, acc[0]);
                acc[1] = ffma2(hv.y, wd0, acc[1]);
                acc[2] = ffma2(hv.x, wd1, acc[2]);
                acc[3] = ffma2(hv.y, wd1, acc[3]);
            }
#pragma unroll
            for (int j = 0; j < 2; j++) {
                float2 v0 = unpack2(acc[j * 2]);
                float2 v1 = unpack2(acc[j * 2 + 1]);
                *(float4*)(hA + l1w + 8 * j + gq * 4) =
                    make_float4(elu1(v0.x), elu1(v0.y), elu1(v1.x), elu1(v1.y));
            }
        }
        __syncthreads();

        // t rolling slot + z prefetch for step s+2
        if (tid == 192) {
            if (s + 2 < Tt) tsh[s & 1] = treg;
            if (s + 3 < Tt) treg = t[s + 3];
        }
        float znext = 0.f;
        if (tid >= 64 && tid < 128 && s + 2 < Tt) znext = z[zbase + (size_t)(s + 2) * 8];

        // ---- layer 2 ----
        biglayerA<false>(w2c, strb, W2, W3, hA, hB, j0q, kq, quadg, 0, b2q, str_u32, tid);
        __syncthreads();

        // ---- layer 3 ----
        biglayerA<true>(w3c, strb, W2, W3, hB, h3p, j0q, kq, quadg, 1, b3q, str_u32, tid);
        __syncthreads();

        // ---- layer 4 partials ----
        {
            float p = 0.f;
            const int base = c4 * 64;
            const float* hp = h3p + g4 * 260 + base;
            const float* wp = w4t + k4 * 260 + base;
#pragma unroll
            for (int it = 0; it < 16; it++) {
                float4 hv = *(const float4*)(hp + it * 4);
                float4 wv = *(const float4*)(wp + it * 4);
                p = fmaf(hv.x, wv.x, p); p = fmaf(hv.y, wv.y, p);
                p = fmaf(hv.z, wv.z, p); p = fmaf(hv.w, wv.w, p);
            }
            red[tid] = p;
        }
        __syncthreads();

        // ---- epilogue ----
        if (tid < 64) {
            int k = tid & 7, g = tid >> 3;
            float o = b4s[k] + red[tid] + red[tid + 64] + red[tid + 128] + red[tid + 192];
            float xn = inp[INROW(k) + g] + dt * o;
            inp[INROW(k) + g] = xn;
            out[(size_t)(b0 + g) * Tt * 8 + (size_t)(s + 1) * 8 + k] = xn;
        } else if (tid < 128) {
            int r = tid - 64, g = r >> 3, zi = r & 7;
            float v = (t1 >= evts[g]) ? zjs[r] : zreg;
            inp[INROW(8 + zi) + g] = v;
            zreg = znext;
        }
        __syncthreads();
    }
}

extern "C" void kernel_launch(void* const* d_in, const int* in_sizes, int n_in,
                              void* d_out, int out_size) {
    const float* t       = (const float*)d_in[0];
    const float* x       = (const float*)d_in[1];
    const float* z       = (const float*)d_in[2];
    const float* event_t = (const float*)d_in[3];
    const float* z_jump  = (const float*)d_in[4];
    const float* W1      = (const float*)d_in[5];
    const float* b1      = (const float*)d_in[6];
    const float* W2      = (const float*)d_in[7];
    const float* b2      = (const float*)d_in[8];
    const float* W3      = (const float*)d_in[9];
    const float* b3      = (const float*)d_in[10];
    const float* W4      = (const float*)d_in[11];
    const float* b4      = (const float*)d_in[12];
    float* out = (float*)d_out;

    cudaFuncSetAttribute(ode_main, cudaFuncAttributeMaxDynamicSharedMemorySize, SM_BYTES);

    ode_main<<<NBLK, NTHR, SM_BYTES>>>(t, x, z, event_t, z_jump,
                                       W1, b1, W2, b2, W3, b3, W4, b4, out);
}